// round 12
// baseline (speedup 1.0000x reference)
#include <cuda_runtime.h>
#include <cuda_bf16.h>
#include <math.h>
#include <stdint.h>

#define BB 2
#define SEQ 2048
#define RR (BB*SEQ)          // 4096 rows
#define DIM 1024
#define HID 2816
#define NH 16
#define HD 64
#define MCOLS (6*DIM)        // 6144
#define KSPLIT 32

// ---- scratch (float units) ----
#define SZ_M     16384
#define SZ_MPART (KSPLIT*2*MCOLS)
#define SZ_RD    (RR*DIM)
#define SZ_RDH   (RR*DIM/2)
#define SZ_RHH   (RR*HID/2)
#define SZ_WS    (DIM*DIM/2)
#define SZ_WB    (DIM*HID/2)

#define OFF_M    0
#define OFF_MPART (OFF_M + SZ_M)
#define OFF_HBF  (OFF_MPART + SZ_MPART)
#define OFF_QF   (OFF_HBF + SZ_RDH)
#define OFF_KF   (OFF_QF + SZ_RD)
#define OFF_QBF  (OFF_KF + SZ_RD)
#define OFF_KBF  (OFF_QBF + SZ_RDH)
#define OFF_VBF  (OFF_KBF + SZ_RDH)
#define OFF_ABF  (OFF_VBF + SZ_RDH)
#define OFF_XMID (OFF_ABF + SZ_RDH)
#define OFF_G1BF (OFF_XMID + SZ_RD)
#define OFF_WQC  (OFF_G1BF + SZ_RHH)
#define OFF_WKC  (OFF_WQC + SZ_WS)
#define OFF_WVC  (OFF_WKC + SZ_WS)
#define OFF_WOC  (OFF_WVC + SZ_WS)
#define OFF_W1C  (OFF_WOC + SZ_WS)
#define OFF_W3C  (OFF_W1C + SZ_WB)
#define OFF_W2C  (OFF_W3C + SZ_WB)
#define TOTAL_F  (OFF_W2C + SZ_WB)

__device__ float g_buf[TOTAL_F];

__device__ __forceinline__ uint32_t smem_u32(const void* p) {
    uint32_t a;
    asm("{ .reg .u64 t; cvta.to.shared.u64 t, %1; cvt.u32.u64 %0, t; }" : "=r"(a) : "l"(p));
    return a;
}

// ===========================================================================
// adaLN split-K (32 splits of 32 k each) + deterministic reduce
// ===========================================================================
__global__ __launch_bounds__(256) void adaln_part_kernel(
    const float* __restrict__ a, const float* __restrict__ W,
    float* __restrict__ mpart)
{
    __shared__ float act0[32], act1[32];
    int j = blockIdx.x * 256 + threadIdx.x;
    int k0 = blockIdx.y * 32;
    if (threadIdx.x < 32) {
        float v = a[k0 + threadIdx.x];
        act0[threadIdx.x] = v / (1.f + __expf(-v));
    } else if (threadIdx.x < 64) {
        float v = a[DIM + k0 + threadIdx.x - 32];
        act1[threadIdx.x - 32] = v / (1.f + __expf(-v));
    }
    __syncthreads();
    float acc0 = 0.f, acc1 = 0.f;
    const float* Wp = W + (size_t)k0 * MCOLS + j;
    #pragma unroll 8
    for (int k = 0; k < 32; k++) {
        float w = Wp[(size_t)k * MCOLS];
        acc0 += act0[k] * w;
        acc1 += act1[k] * w;
    }
    mpart[(blockIdx.y*2 + 0)*MCOLS + j] = acc0;
    mpart[(blockIdx.y*2 + 1)*MCOLS + j] = acc1;
}

__global__ __launch_bounds__(256) void adaln_reduce_kernel(
    const float* __restrict__ mpart, const float* __restrict__ bias,
    float* __restrict__ m)
{
    int j = blockIdx.x * 256 + threadIdx.x;
    float b = bias[j];
    float s0 = b, s1 = b;
    #pragma unroll
    for (int kz = 0; kz < KSPLIT; kz++) {
        s0 += mpart[(kz*2 + 0)*MCOLS + j];
        s1 += mpart[(kz*2 + 1)*MCOLS + j];
    }
    m[j] = s0;
    m[MCOLS + j] = s1;
}

// ===========================================================================
// streaming fp32 -> bf16 converts
// ===========================================================================
__device__ __forceinline__ void conv8(const float* s, __nv_bfloat16* d, int i) {
    float4 a = *(const float4*)(s + i);
    float4 b = *(const float4*)(s + i + 4);
    __nv_bfloat162 p0 = __floats2bfloat162_rn(a.x, a.y);
    __nv_bfloat162 p1 = __floats2bfloat162_rn(a.z, a.w);
    __nv_bfloat162 p2 = __floats2bfloat162_rn(b.x, b.y);
    __nv_bfloat162 p3 = __floats2bfloat162_rn(b.z, b.w);
    uint4 o;
    o.x = *(uint32_t*)&p0; o.y = *(uint32_t*)&p1;
    o.z = *(uint32_t*)&p2; o.w = *(uint32_t*)&p3;
    *(uint4*)(d + i) = o;
}

__global__ __launch_bounds__(256) void convert2_kernel(
    const float* __restrict__ s0, const float* __restrict__ s1,
    __nv_bfloat16* __restrict__ d0, __nv_bfloat16* __restrict__ d1)
{
    const float* s = blockIdx.y ? s1 : s0;
    __nv_bfloat16* d = blockIdx.y ? d1 : d0;
    conv8(s, d, (blockIdx.x*256 + threadIdx.x)*8);
}

__global__ __launch_bounds__(256) void convert3_kernel(
    const float* __restrict__ s0, const float* __restrict__ s1, const float* __restrict__ s2,
    __nv_bfloat16* __restrict__ d0, __nv_bfloat16* __restrict__ d1, __nv_bfloat16* __restrict__ d2)
{
    const float* s = (blockIdx.y == 0) ? s0 : (blockIdx.y == 1) ? s1 : s2;
    __nv_bfloat16* d = (blockIdx.y == 0) ? d0 : (blockIdx.y == 1) ? d1 : d2;
    conv8(s, d, (blockIdx.x*256 + threadIdx.x)*8);
}

// ===========================================================================
// rmsnorm + modulate -> bf16
// ===========================================================================
__global__ __launch_bounds__(256) void rmsmod_kernel(
    const float* __restrict__ src, const float* __restrict__ w,
    const float* __restrict__ m, int shift_off, int scale_off,
    __nv_bfloat16* __restrict__ dst)
{
    __shared__ float red[256];
    int row = blockIdx.x;
    int b = row >> 11;
    int tid = threadIdx.x;
    float4 v = ((const float4*)(src + (size_t)row*DIM))[tid];
    red[tid] = v.x*v.x + v.y*v.y + v.z*v.z + v.w*v.w;
    __syncthreads();
    for (int s = 128; s > 0; s >>= 1) {
        if (tid < s) red[tid] += red[tid+s];
        __syncthreads();
    }
    float rms = rsqrtf(red[0] * (1.f/DIM) + 1e-5f);
    int d = tid * 4;
    float4 wv = *(const float4*)(w + d);
    float4 sh = *(const float4*)(m + b*MCOLS + shift_off + d);
    float4 sc = *(const float4*)(m + b*MCOLS + scale_off + d);
    float o0 = v.x*rms*wv.x*(1.f+sc.x) + sh.x;
    float o1 = v.y*rms*wv.y*(1.f+sc.y) + sh.y;
    float o2 = v.z*rms*wv.z*(1.f+sc.z) + sh.z;
    float o3 = v.w*rms*wv.w*(1.f+sc.w) + sh.w;
    __nv_bfloat162* dp = (__nv_bfloat162*)(dst + (size_t)row*DIM);
    dp[tid*2]   = __floats2bfloat162_rn(o0, o1);
    dp[tid*2+1] = __floats2bfloat162_rn(o2, o3);
}

// ===========================================================================
// bf16 mma GEMM, BK=64, 3-stage cp.async, 2 CTAs/SM (reg cap 128).
// MODE 2: C = xres + gate*acc (fp32). MODE 3: fused QKV.
// ===========================================================================
#define GSMEM (3*32768)

template<int MODE>
__global__ __launch_bounds__(256, 2) void mma_gemm_kernel(
    const __nv_bfloat16* __restrict__ A,
    const __nv_bfloat16* __restrict__ B0,
    const __nv_bfloat16* __restrict__ B1m,
    const __nv_bfloat16* __restrict__ B2m,
    int ldb,
    float* __restrict__ Cf,
    float* __restrict__ kf,
    __nv_bfloat16* __restrict__ vbf,
    const float* __restrict__ xres,
    const float* __restrict__ mvec, int gate_off,
    int M, int N, int K)
{
    extern __shared__ __align__(128) char smch[];
    uint32_t sb = smem_u32(smch);
    int tid = threadIdx.x;
    int wid = tid >> 5, lid = tid & 31;
    int warp_m = wid & 1;
    int warp_n = wid >> 1;
    int row0 = blockIdx.y * 128;
    int col0 = blockIdx.x * 128;
    int iters = K >> 6;

    const __nv_bfloat16* B = B0;
    int msel = 0, colB = col0;
    if (MODE == 3) {
        msel = col0 >> 10;
        colB = col0 & 1023;
        B = (msel == 0) ? B0 : (msel == 1) ? B1m : B2m;
    }

    // A tile: 128 rows x 128B (8 chunks); 1024 chunks -> 4 per thread
    uint32_t soA[4]; const char* gA[4];
    #pragma unroll
    for (int i = 0; i < 4; i++) {
        int cid = tid + 256*i;
        int row = cid >> 3, ch = cid & 7;
        soA[i] = row*128 + ((ch ^ (row & 7)) << 4);
        gA[i] = (const char*)(A + (size_t)(row0 + row)*K) + ch*16;
    }
    // B tile: 64 rows x 256B (16 chunks); 1024 chunks -> 4 per thread
    uint32_t soB[4]; const char* gB[4];
    #pragma unroll
    for (int i = 0; i < 4; i++) {
        int cid = tid + 256*i;
        int rb = cid >> 4, cb = cid & 15;
        soB[i] = rb*256 + ((cb ^ (rb & 7)) << 4);
        gB[i] = (const char*)(B + (size_t)rb*ldb + colB) + cb*16;
    }
    size_t bstep = (size_t)64 * ldb * 2;

    float acc[4][4][4];
    #pragma unroll
    for (int i = 0; i < 4; i++)
        #pragma unroll
        for (int j = 0; j < 4; j++)
            #pragma unroll
            for (int q = 0; q < 4; q++) acc[i][j][q] = 0.f;

    int arow[4];
    #pragma unroll
    for (int mt = 0; mt < 4; mt++)
        arow[mt] = warp_m*64 + mt*16 + (lid & 15);
    int ahalf = lid >> 4;
    int matq = lid >> 3, r8 = lid & 7;

    #pragma unroll
    for (int p = 0; p < 2; p++) {
        uint32_t tA = sb + p*32768, tB = tA + 16384;
        #pragma unroll
        for (int i = 0; i < 4; i++) {
            asm volatile("cp.async.cg.shared.global [%0], [%1], 16;" :: "r"(tA+soA[i]), "l"(gA[i] + p*128));
            asm volatile("cp.async.cg.shared.global [%0], [%1], 16;" :: "r"(tB+soB[i]), "l"(gB[i] + p*bstep));
        }
        asm volatile("cp.async.commit_group;");
    }

    int sidx = 0, pidx = 2;
    for (int kt = 0; kt < iters; kt++) {
        if (kt < iters-1) asm volatile("cp.async.wait_group 1;" ::: "memory");
        else              asm volatile("cp.async.wait_group 0;" ::: "memory");
        __syncthreads();

        if (kt + 2 < iters) {
            uint32_t tA = sb + pidx*32768, tB = tA + 16384;
            size_t ka = (size_t)(kt + 2) * 128;
            size_t kb = (size_t)(kt + 2) * bstep;
            #pragma unroll
            for (int i = 0; i < 4; i++) {
                asm volatile("cp.async.cg.shared.global [%0], [%1], 16;" :: "r"(tA+soA[i]), "l"(gA[i]+ka));
                asm volatile("cp.async.cg.shared.global [%0], [%1], 16;" :: "r"(tB+soB[i]), "l"(gB[i]+kb));
            }
            asm volatile("cp.async.commit_group;");
        }

        uint32_t sA = sb + sidx*32768, sB = sA + 16384;
        #pragma unroll
        for (int ks = 0; ks < 4; ks++) {
            uint32_t a[4][4], b[4][2];
            #pragma unroll
            for (int mt = 0; mt < 4; mt++) {
                int row = arow[mt];
                int ck = ks*2 + ahalf;
                uint32_t ad = sA + row*128 + ((ck ^ (row & 7)) << 4);
                asm volatile("ldmatrix.sync.aligned.m8n8.x4.shared.b16 {%0,%1,%2,%3}, [%4];"
                    : "=r"(a[mt][0]), "=r"(a[mt][1]), "=r"(a[mt][2]), "=r"(a[mt][3]) : "r"(ad));
            }
            #pragma unroll
            for (int nt2 = 0; nt2 < 2; nt2++) {
                int krow = ks*16 + ((matq & 1) << 3) + r8;
                int ch = warp_n*4 + nt2*2 + (matq >> 1);
                uint32_t ad = sB + krow*256 + ((ch ^ (krow & 7)) << 4);
                asm volatile("ldmatrix.sync.aligned.m8n8.x4.trans.shared.b16 {%0,%1,%2,%3}, [%4];"
                    : "=r"(b[nt2*2][0]), "=r"(b[nt2*2][1]),
                      "=r"(b[nt2*2+1][0]), "=r"(b[nt2*2+1][1]) : "r"(ad));
            }
            #pragma unroll
            for (int mt = 0; mt < 4; mt++)
                #pragma unroll
                for (int nt = 0; nt < 4; nt++) {
                    asm volatile(
                        "mma.sync.aligned.m16n8k16.row.col.f32.bf16.bf16.f32 "
                        "{%0,%1,%2,%3}, {%4,%5,%6,%7}, {%8,%9}, {%0,%1,%2,%3};"
                        : "+f"(acc[mt][nt][0]), "+f"(acc[mt][nt][1]),
                          "+f"(acc[mt][nt][2]), "+f"(acc[mt][nt][3])
                        : "r"(a[mt][0]), "r"(a[mt][1]), "r"(a[mt][2]), "r"(a[mt][3]),
                          "r"(b[nt][0]), "r"(b[nt][1]));
                }
        }
        sidx = (sidx == 2) ? 0 : sidx + 1;
        pidx = (pidx == 2) ? 0 : pidx + 1;
    }

    int lr = lid >> 2;
    int lc = (lid & 3) * 2;
    if (MODE == 2) {
        int bsel = row0 >> 11;
        const float* gv = mvec + bsel*MCOLS + gate_off;
        #pragma unroll
        for (int mt = 0; mt < 4; mt++) {
            size_t mrow = (size_t)(row0 + warp_m*64 + mt*16 + lr);
            #pragma unroll
            for (int nt = 0; nt < 4; nt++) {
                int col = col0 + warp_n*32 + nt*8 + lc;
                float2 g = *(const float2*)(gv + col);
                float2 x0 = *(const float2*)(xres + mrow*N + col);
                float2 x1 = *(const float2*)(xres + (mrow+8)*N + col);
                *(float2*)(Cf + mrow*N + col) =
                    make_float2(x0.x + g.x*acc[mt][nt][0], x0.y + g.y*acc[mt][nt][1]);
                *(float2*)(Cf + (mrow+8)*N + col) =
                    make_float2(x1.x + g.x*acc[mt][nt][2], x1.y + g.y*acc[mt][nt][3]);
            }
        }
    } else {  // MODE 3
        #pragma unroll
        for (int mt = 0; mt < 4; mt++) {
            size_t mrow = (size_t)(row0 + warp_m*64 + mt*16 + lr);
            #pragma unroll
            for (int nt = 0; nt < 4; nt++) {
                int col = colB + warp_n*32 + nt*8 + lc;
                if (msel == 2) {
                    *(__nv_bfloat162*)(vbf + mrow*DIM + col) =
                        __floats2bfloat162_rn(acc[mt][nt][0], acc[mt][nt][1]);
                    *(__nv_bfloat162*)(vbf + (mrow+8)*DIM + col) =
                        __floats2bfloat162_rn(acc[mt][nt][2], acc[mt][nt][3]);
                } else {
                    float* dst = msel ? kf : Cf;
                    *(float2*)(dst + mrow*DIM + col) =
                        make_float2(acc[mt][nt][0], acc[mt][nt][1]);
                    *(float2*)(dst + (mrow+8)*DIM + col) =
                        make_float2(acc[mt][nt][2], acc[mt][nt][3]);
                }
            }
        }
    }
}

// ===========================================================================
// Fused FFN dual GEMM, BK=64, 2 CTAs/SM: g = bf16( silu(A@W1) * (A@W3) )
// ===========================================================================
#define FSMEM (3*32768)

__global__ __launch_bounds__(256, 2) void ffn_gemm_kernel(
    const __nv_bfloat16* __restrict__ A,
    const __nv_bfloat16* __restrict__ W1c,
    const __nv_bfloat16* __restrict__ W3c,
    __nv_bfloat16* __restrict__ Og, int M, int N, int K)
{
    extern __shared__ __align__(128) char smch[];
    uint32_t sb = smem_u32(smch);
    int tid = threadIdx.x;
    int wid = tid >> 5, lid = tid & 31;
    int warp_m = wid & 1;
    int warp_n = wid >> 1;
    int row0 = blockIdx.y * 128;
    int col0 = blockIdx.x * 64;
    int iters = K >> 6;

    uint32_t soA[4]; const char* gA[4];
    #pragma unroll
    for (int i = 0; i < 4; i++) {
        int cid = tid + 256*i;
        int row = cid >> 3, ch = cid & 7;
        soA[i] = row*128 + ((ch ^ (row & 7)) << 4);
        gA[i] = (const char*)(A + (size_t)(row0 + row)*K) + ch*16;
    }
    uint32_t soB[2]; const char *g1[2], *g3[2];
    #pragma unroll
    for (int i = 0; i < 2; i++) {
        int cid = tid + 256*i;
        int rb = cid >> 3, cb = cid & 7;
        soB[i] = rb*128 + ((cb ^ (rb & 7)) << 4);
        g1[i] = (const char*)(W1c + (size_t)rb*N + col0) + cb*16;
        g3[i] = (const char*)(W3c + (size_t)rb*N + col0) + cb*16;
    }
    size_t bstep = (size_t)64 * N * 2;

    float acc1[4][2][4], acc3[4][2][4];
    #pragma unroll
    for (int i = 0; i < 4; i++)
        #pragma unroll
        for (int j = 0; j < 2; j++)
            #pragma unroll
            for (int q = 0; q < 4; q++) { acc1[i][j][q] = 0.f; acc3[i][j][q] = 0.f; }

    int arow[4];
    #pragma unroll
    for (int mt = 0; mt < 4; mt++)
        arow[mt] = warp_m*64 + mt*16 + (lid & 15);
    int ahalf = lid >> 4;
    int matq = lid >> 3, r8 = lid & 7;

    #pragma unroll
    for (int p = 0; p < 2; p++) {
        uint32_t tA = sb + p*32768, tB1 = tA + 16384, tB3 = tA + 24576;
        #pragma unroll
        for (int i = 0; i < 4; i++)
            asm volatile("cp.async.cg.shared.global [%0], [%1], 16;" :: "r"(tA+soA[i]), "l"(gA[i] + p*128));
        #pragma unroll
        for (int i = 0; i < 2; i++) {
            asm volatile("cp.async.cg.shared.global [%0], [%1], 16;" :: "r"(tB1+soB[i]), "l"(g1[i] + p*bstep));
            asm volatile("cp.async.cg.shared.global [%0], [%1], 16;" :: "r"(tB3+soB[i]), "l"(g3[i] + p*bstep));
        }
        asm volatile("cp.async.commit_group;");
    }

    int sidx = 0, pidx = 2;
    for (int kt = 0; kt < iters; kt++) {
        if (kt < iters-1) asm volatile("cp.async.wait_group 1;" ::: "memory");
        else              asm volatile("cp.async.wait_group 0;" ::: "memory");
        __syncthreads();

        if (kt + 2 < iters) {
            uint32_t tA = sb + pidx*32768, tB1 = tA + 16384, tB3 = tA + 24576;
            size_t ka = (size_t)(kt + 2) * 128;
            size_t kb = (size_t)(kt + 2) * bstep;
            #pragma unroll
            for (int i = 0; i < 4; i++)
                asm volatile("cp.async.cg.shared.global [%0], [%1], 16;" :: "r"(tA+soA[i]), "l"(gA[i]+ka));
            #pragma unroll
            for (int i = 0; i < 2; i++) {
                asm volatile("cp.async.cg.shared.global [%0], [%1], 16;" :: "r"(tB1+soB[i]), "l"(g1[i]+kb));
                asm volatile("cp.async.cg.shared.global [%0], [%1], 16;" :: "r"(tB3+soB[i]), "l"(g3[i]+kb));
            }
            asm volatile("cp.async.commit_group;");
        }

        uint32_t sA = sb + sidx*32768, sB1 = sA + 16384, sB3 = sA + 24576;
        #pragma unroll
        for (int ks = 0; ks < 4; ks++) {
            uint32_t a[4][4];
            #pragma unroll
            for (int mt = 0; mt < 4; mt++) {
                int row = arow[mt];
                int ck = ks*2 + ahalf;
                uint32_t ad = sA + row*128 + ((ck ^ (row & 7)) << 4);
                asm volatile("ldmatrix.sync.aligned.m8n8.x4.shared.b16 {%0,%1,%2,%3}, [%4];"
                    : "=r"(a[mt][0]), "=r"(a[mt][1]), "=r"(a[mt][2]), "=r"(a[mt][3]) : "r"(ad));
            }
            int krow = ks*16 + ((matq & 1) << 3) + r8;
            int ch = warp_n*2 + (matq >> 1);
            uint32_t swoff = krow*128 + ((ch ^ (krow & 7)) << 4);
            uint32_t b1[4], b3[4];
            asm volatile("ldmatrix.sync.aligned.m8n8.x4.trans.shared.b16 {%0,%1,%2,%3}, [%4];"
                : "=r"(b1[0]), "=r"(b1[1]), "=r"(b1[2]), "=r"(b1[3]) : "r"(sB1 + swoff));
            asm volatile("ldmatrix.sync.aligned.m8n8.x4.trans.shared.b16 {%0,%1,%2,%3}, [%4];"
                : "=r"(b3[0]), "=r"(b3[1]), "=r"(b3[2]), "=r"(b3[3]) : "r"(sB3 + swoff));
            #pragma unroll
            for (int mt = 0; mt < 4; mt++) {
                #pragma unroll
                for (int nt = 0; nt < 2; nt++) {
                    asm volatile(
                        "mma.sync.aligned.m16n8k16.row.col.f32.bf16.bf16.f32 "
                        "{%0,%1,%2,%3}, {%4,%5,%6,%7}, {%8,%9}, {%0,%1,%2,%3};"
                        : "+f"(acc1[mt][nt][0]), "+f"(acc1[mt][nt][1]),
                          "+f"(acc1[mt][nt][2]), "+f"(acc1[mt][nt][3])
                        : "r"(a[mt][0]), "r"(a[mt][1]), "r"(a[mt][2]), "r"(a[mt][3]),
                          "r"(b1[nt*2]), "r"(b1[nt*2+1]));
                    asm volatile(
                        "mma.sync.aligned.m16n8k16.row.col.f32.bf16.bf16.f32 "
                        "{%0,%1,%2,%3}, {%4,%5,%6,%7}, {%8,%9}, {%0,%1,%2,%3};"
                        : "+f"(acc3[mt][nt][0]), "+f"(acc3[mt][nt][1]),
                          "+f"(acc3[mt][nt][2]), "+f"(acc3[mt][nt][3])
                        : "r"(a[mt][0]), "r"(a[mt][1]), "r"(a[mt][2]), "r"(a[mt][3]),
                          "r"(b3[nt*2]), "r"(b3[nt*2+1]));
                }
            }
        }
        sidx = (sidx == 2) ? 0 : sidx + 1;
        pidx = (pidx == 2) ? 0 : pidx + 1;
    }

    int lr = lid >> 2;
    int lc = (lid & 3) * 2;
    #pragma unroll
    for (int mt = 0; mt < 4; mt++) {
        size_t mrow = (size_t)(row0 + warp_m*64 + mt*16 + lr);
        #pragma unroll
        for (int nt = 0; nt < 2; nt++) {
            int col = col0 + warp_n*16 + nt*8 + lc;
            float s0 = acc1[mt][nt][0], s1 = acc1[mt][nt][1];
            float s2 = acc1[mt][nt][2], s3 = acc1[mt][nt][3];
            float o0 = s0 / (1.f + __expf(-s0)) * acc3[mt][nt][0];
            float o1 = s1 / (1.f + __expf(-s1)) * acc3[mt][nt][1];
            float o2 = s2 / (1.f + __expf(-s2)) * acc3[mt][nt][2];
            float o3 = s3 / (1.f + __expf(-s3)) * acc3[mt][nt][3];
            *(__nv_bfloat162*)(Og + mrow*N + col)     = __floats2bfloat162_rn(o0, o1);
            *(__nv_bfloat162*)(Og + (mrow+8)*N + col) = __floats2bfloat162_rn(o2, o3);
        }
    }
}

// ===========================================================================
// layernorm + RoPE for q and k in one launch
// ===========================================================================
__global__ __launch_bounds__(256) void lnrope2_kernel(
    const float* __restrict__ qf, const float* __restrict__ kf,
    const float* __restrict__ qw, const float* __restrict__ qb,
    const float* __restrict__ kw, const float* __restrict__ kb,
    const float* __restrict__ cosT, const float* __restrict__ sinT,
    __nv_bfloat16* __restrict__ qbf, __nv_bfloat16* __restrict__ kbf)
{
    __shared__ float redm[256], redv[256];
    int sel = blockIdx.y;
    const float* t = sel ? kf : qf;
    const float* w = sel ? kw : qw;
    const float* bvec = sel ? kb : qb;
    __nv_bfloat16* dst = sel ? kbf : qbf;
    int row = blockIdx.x;
    int s = row & (SEQ-1);
    int tid = threadIdx.x;
    float4 v = ((const float4*)(t + (size_t)row*DIM))[tid];
    redm[tid] = v.x + v.y + v.z + v.w;
    redv[tid] = v.x*v.x + v.y*v.y + v.z*v.z + v.w*v.w;
    __syncthreads();
    for (int st = 128; st > 0; st >>= 1) {
        if (tid < st) { redm[tid] += redm[tid+st]; redv[tid] += redv[tid+st]; }
        __syncthreads();
    }
    float mu = redm[0] * (1.f/DIM);
    float var = redv[0] * (1.f/DIM) - mu*mu;
    float rs = rsqrtf(var + 1e-5f);
    int d = tid*4;
    float4 wv = *(const float4*)(w + d);
    float4 bv = *(const float4*)(bvec + d);
    float y0 = (v.x-mu)*rs*wv.x + bv.x;
    float y1 = (v.y-mu)*rs*wv.y + bv.y;
    float y2 = (v.z-mu)*rs*wv.z + bv.z;
    float y3 = (v.w-mu)*rs*wv.w + bv.w;
    int i0 = (d & 63) >> 1;
    float c0 = cosT[s*32 + i0],   s0 = sinT[s*32 + i0];
    float c1 = cosT[s*32 + i0+1], s1 = sinT[s*32 + i0+1];
    float o0 = y0*c0 - y1*s0;
    float o1 = y0*s0 + y1*c0;
    float o2 = y2*c1 - y3*s1;
    float o3 = y2*s1 + y3*c1;
    __nv_bfloat162* dp = (__nv_bfloat162*)(dst + (size_t)row*DIM);
    dp[tid*2]   = __floats2bfloat162_rn(o0, o1);
    dp[tid*2+1] = __floats2bfloat162_rn(o2, o3);
}

// ===========================================================================
// Tensor-core flash attention
// ===========================================================================
#define ATT_SMEM 49152

__global__ __launch_bounds__(256, 1) void attn_mma_kernel(
    const __nv_bfloat16* __restrict__ q, const __nv_bfloat16* __restrict__ k,
    const __nv_bfloat16* __restrict__ v, __nv_bfloat16* __restrict__ o)
{
    extern __shared__ __align__(128) char smch[];
    uint32_t sb = smem_u32(smch);
    const uint32_t sq  = sb;
    const uint32_t sk0 = sb + 16384;
    const uint32_t sv0 = sb + 32768;
    int tid = threadIdx.x, wid = tid >> 5, lid = tid & 31;
    int qt = blockIdx.x, h = blockIdx.y, b = blockIdx.z;
    int hoffb = h * HD * 2;
    int qbase = b*SEQ + qt*128;
    int kbb   = b*SEQ;

    #pragma unroll
    for (int i = 0; i < 4; i++) {
        int cid = tid + 256*i;
        int row = cid >> 3, ch = cid & 7;
        const char* g = (const char*)(q + (size_t)(qbase+row)*DIM) + hoffb + ch*16;
        uint32_t so = sq + row*128 + ((ch ^ (row & 7)) << 4);
        asm volatile("cp.async.cg.shared.global [%0], [%1], 16;" :: "r"(so), "l"(g));
    }
    #pragma unroll
    for (int i = 0; i < 2; i++) {
        int cid = tid + 256*i;
        int row = cid >> 3, ch = cid & 7;
        uint32_t so = row*128 + ((ch ^ (row & 7)) << 4);
        const char* gk = (const char*)(k + (size_t)(kbb+row)*DIM) + hoffb + ch*16;
        const char* gv = (const char*)(v + (size_t)(kbb+row)*DIM) + hoffb + ch*16;
        asm volatile("cp.async.cg.shared.global [%0], [%1], 16;" :: "r"(sk0+so), "l"(gk));
        asm volatile("cp.async.cg.shared.global [%0], [%1], 16;" :: "r"(sv0+so), "l"(gv));
    }
    asm volatile("cp.async.commit_group;");

    int wr = wid * 16;
    uint32_t qf[4][4];
    float oacc[8][4];
    #pragma unroll
    for (int j = 0; j < 8; j++)
        #pragma unroll
        for (int i = 0; i < 4; i++) oacc[j][i] = 0.f;
    float m0 = -INFINITY, m1 = -INFINITY, l0 = 0.f, l1 = 0.f;

    for (int kt = 0; kt < SEQ/64; kt++) {
        int s = kt & 1;
        if (kt + 1 < SEQ/64) {
            int ns = s ^ 1;
            int kb2 = kbb + (kt+1)*64;
            #pragma unroll
            for (int i = 0; i < 2; i++) {
                int cid = tid + 256*i;
                int row = cid >> 3, ch = cid & 7;
                uint32_t so = row*128 + ((ch ^ (row & 7)) << 4);
                const char* gk = (const char*)(k + (size_t)(kb2+row)*DIM) + hoffb + ch*16;
                const char* gv = (const char*)(v + (size_t)(kb2+row)*DIM) + hoffb + ch*16;
                asm volatile("cp.async.cg.shared.global [%0], [%1], 16;" :: "r"(sk0+ns*8192+so), "l"(gk));
                asm volatile("cp.async.cg.shared.global [%0], [%1], 16;" :: "r"(sv0+ns*8192+so), "l"(gv));
            }
            asm volatile("cp.async.commit_group;");
            asm volatile("cp.async.wait_group 1;" ::: "memory");
        } else {
            asm volatile("cp.async.wait_group 0;" ::: "memory");
        }
        __syncthreads();

        if (kt == 0) {
            int arow2 = wr + (lid & 15);
            #pragma unroll
            for (int s2 = 0; s2 < 4; s2++) {
                int ch = 2*s2 + (lid >> 4);
                uint32_t ad = sq + arow2*128 + ((ch ^ (arow2 & 7)) << 4);
                asm volatile("ldmatrix.sync.aligned.m8n8.x4.shared.b16 {%0,%1,%2,%3}, [%4];"
                    : "=r"(qf[s2][0]), "=r"(qf[s2][1]), "=r"(qf[s2][2]), "=r"(qf[s2][3]) : "r"(ad));
            }
        }
        uint32_t skst = sk0 + s*8192, svst = sv0 + s*8192;

        float sa[8][4];
        #pragma unroll
        for (int j = 0; j < 8; j++)
            #pragma unroll
            for (int i = 0; i < 4; i++) sa[j][i] = 0.f;

        #pragma unroll
        for (int s2 = 0; s2 < 4; s2++) {
            #pragma unroll
            for (int p = 0; p < 4; p++) {
                int mat = lid >> 3;
                int krow = p*16 + ((mat >> 1) << 3) + (lid & 7);
                int ch = 2*s2 + (mat & 1);
                uint32_t ad = skst + krow*128 + ((ch ^ (krow & 7)) << 4);
                uint32_t b0, b1, b2, b3;
                asm volatile("ldmatrix.sync.aligned.m8n8.x4.shared.b16 {%0,%1,%2,%3}, [%4];"
                    : "=r"(b0), "=r"(b1), "=r"(b2), "=r"(b3) : "r"(ad));
                asm volatile(
                    "mma.sync.aligned.m16n8k16.row.col.f32.bf16.bf16.f32 "
                    "{%0,%1,%2,%3}, {%4,%5,%6,%7}, {%8,%9}, {%0,%1,%2,%3};"
                    : "+f"(sa[2*p][0]), "+f"(sa[2*p][1]), "+f"(sa[2*p][2]), "+f"(sa[2*p][3])
                    : "r"(qf[s2][0]), "r"(qf[s2][1]), "r"(qf[s2][2]), "r"(qf[s2][3]),
                      "r"(b0), "r"(b1));
                asm volatile(
                    "mma.sync.aligned.m16n8k16.row.col.f32.bf16.bf16.f32 "
                    "{%0,%1,%2,%3}, {%4,%5,%6,%7}, {%8,%9}, {%0,%1,%2,%3};"
                    : "+f"(sa[2*p+1][0]), "+f"(sa[2*p+1][1]), "+f"(sa[2*p+1][2]), "+f"(sa[2*p+1][3])
                    : "r"(qf[s2][0]), "r"(qf[s2][1]), "r"(qf[s2][2]), "r"(qf[s2][3]),
                      "r"(b2), "r"(b3));
            }
        }

        float mx0 = -INFINITY, mx1 = -INFINITY;
        #pragma unroll
        for (int j = 0; j < 8; j++) {
            sa[j][0] *= 0.125f; sa[j][1] *= 0.125f;
            sa[j][2] *= 0.125f; sa[j][3] *= 0.125f;
            mx0 = fmaxf(mx0, fmaxf(sa[j][0], sa[j][1]));
            mx1 = fmaxf(mx1, fmaxf(sa[j][2], sa[j][3]));
        }
        mx0 = fmaxf(mx0, __shfl_xor_sync(0xffffffffu, mx0, 1));
        mx0 = fmaxf(mx0, __shfl_xor_sync(0xffffffffu, mx0, 2));
        mx1 = fmaxf(mx1, __shfl_xor_sync(0xffffffffu, mx1, 1));
        mx1 = fmaxf(mx1, __shfl_xor_sync(0xffffffffu, mx1, 2));
        float nm0 = fmaxf(m0, mx0), nm1 = fmaxf(m1, mx1);

        float ps0 = 0.f, ps1 = 0.f;
        uint32_t pf[4][4];
        #pragma unroll
        for (int j = 0; j < 8; j++) {
            float e0 = __expf(sa[j][0] - nm0);
            float e1 = __expf(sa[j][1] - nm0);
            float e2 = __expf(sa[j][2] - nm1);
            float e3 = __expf(sa[j][3] - nm1);
            ps0 += e0 + e1; ps1 += e2 + e3;
            int s2 = j >> 1;
            __nv_bfloat162 lo = __floats2bfloat162_rn(e0, e1);
            __nv_bfloat162 hi = __floats2bfloat162_rn(e2, e3);
            if ((j & 1) == 0) {
                pf[s2][0] = *(uint32_t*)&lo;
                pf[s2][1] = *(uint32_t*)&hi;
            } else {
                pf[s2][2] = *(uint32_t*)&lo;
                pf[s2][3] = *(uint32_t*)&hi;
            }
        }
        ps0 += __shfl_xor_sync(0xffffffffu, ps0, 1);
        ps0 += __shfl_xor_sync(0xffffffffu, ps0, 2);
        ps1 += __shfl_xor_sync(0xffffffffu, ps1, 1);
        ps1 += __shfl_xor_sync(0xffffffffu, ps1, 2);

        float c0 = __expf(m0 - nm0), c1 = __expf(m1 - nm1);
        l0 = l0*c0 + ps0;  l1 = l1*c1 + ps1;
        m0 = nm0;  m1 = nm1;
        #pragma unroll
        for (int j = 0; j < 8; j++) {
            oacc[j][0] *= c0; oacc[j][1] *= c0;
            oacc[j][2] *= c1; oacc[j][3] *= c1;
        }

        #pragma unroll
        for (int s2 = 0; s2 < 4; s2++) {
            #pragma unroll
            for (int p = 0; p < 4; p++) {
                int mat = lid >> 3;
                int vrow = s2*16 + ((mat & 1) << 3) + (lid & 7);
                int ch = 2*p + (mat >> 1);
                uint32_t ad = svst + vrow*128 + ((ch ^ (vrow & 7)) << 4);
                uint32_t v0, v1, v2, v3;
                asm volatile("ldmatrix.sync.aligned.m8n8.x4.trans.shared.b16 {%0,%1,%2,%3}, [%4];"
                    : "=r"(v0), "=r"(v1), "=r"(v2), "=r"(v3) : "r"(ad));
                asm volatile(
                    "mma.sync.aligned.m16n8k16.row.col.f32.bf16.bf16.f32 "
                    "{%0,%1,%2,%3}, {%4,%5,%6,%7}, {%8,%9}, {%0,%1,%2,%3};"
                    : "+f"(oacc[2*p][0]), "+f"(oacc[2*p][1]), "+f"(oacc[2*p][2]), "+f"(oacc[2*p][3])
                    : "r"(pf[s2][0]), "r"(pf[s2][1]), "r"(pf[s2][2]), "r"(pf[s2][3]),
                      "r"(v0), "r"(v1));
                asm volatile(
                    "mma.sync.aligned.m16n8k16.row.col.f32.bf16.bf16.f32 "
                    "{%0,%1,%2,%3}, {%4,%5,%6,%7}, {%8,%9}, {%0,%1,%2,%3};"
                    : "+f"(oacc[2*p+1][0]), "+f"(oacc[2*p+1][1]), "+f"(oacc[2*p+1][2]), "+f"(oacc[2*p+1][3])
                    : "r"(pf[s2][0]), "r"(pf[s2][1]), "r"(pf[s2][2]), "r"(pf[s2][3]),
                      "r"(v2), "r"(v3));
            }
        }
        __syncthreads();
    }

    float inv0 = 1.f / l0, inv1 = 1.f / l1;
    int r = lid >> 2, c2 = (lid & 3) * 2;
    size_t row0 = (size_t)(qbase + wr + r)*DIM + h*HD + c2;
    size_t row1 = row0 + 8*DIM;
    #pragma unroll
    for (int j = 0; j < 8; j++) {
        *(__nv_bfloat162*)(o + row0 + 8*j) =
            __floats2bfloat162_rn(oacc[j][0]*inv0, oacc[j][1]*inv0);
        *(__nv_bfloat162*)(o + row1 + 8*j) =
            __floats2bfloat162_rn(oacc[j][2]*inv1, oacc[j][3]*inv1);
    }
}

// ===========================================================================
extern "C" void kernel_launch(void* const* d_in, const int* in_sizes, int n_in,
                              void* d_out, int out_size)
{
    const float* x        = (const float*)d_in[0];
    const float* adaln_in = (const float*)d_in[1];
    const float* cosT     = (const float*)d_in[2];
    const float* sinT     = (const float*)d_in[3];
    const float* wq       = (const float*)d_in[4];
    const float* wk       = (const float*)d_in[5];
    const float* wv       = (const float*)d_in[6];
    const float* wo       = (const float*)d_in[7];
    const float* q_norm_w = (const float*)d_in[8];
    const float* q_norm_b = (const float*)d_in[9];
    const float* k_norm_w = (const float*)d_in[10];
    const float* k_norm_b = (const float*)d_in[11];
    const float* attn_norm_w = (const float*)d_in[12];
    const float* ffn_norm_w  = (const float*)d_in[13];
    const float* ada_w    = (const float*)d_in[14];
    const float* ada_b    = (const float*)d_in[15];
    const float* w1       = (const float*)d_in[16];
    const float* w2       = (const float*)d_in[17];
    const float* w3       = (const float*)d_in[18];
    float* out = (float*)d_out;

    float* base = nullptr;
    cudaGetSymbolAddress((void**)&base, g_buf);
    float* m     = base + OFF_M;
    float* mpart = base + OFF_MPART;
    __nv_bfloat16* hbf  = (__nv_bfloat16*)(base + OFF_HBF);
    float* qf   = base + OFF_QF;
    float* kf   = base + OFF_KF;
    __nv_bfloat16* qbf  = (__nv_bfloat16*)(base + OFF_QBF);
    __nv_bfloat16* kbf  = (__nv_bfloat16*)(base + OFF_KBF);
    __nv_bfloat16* vbf  = (__nv_bfloat16*)(base + OFF_VBF);
    __nv_bfloat16* abf  = (__nv_bfloat16*)(base + OFF_ABF);
    float* xmid = base + OFF_XMID;
    __nv_bfloat16* g1bf = (__nv_bfloat16*)(base + OFF_G1BF);
    __nv_bfloat16* wqC  = (__nv_bfloat16*)(base + OFF_WQC);
    __nv_bfloat16* wkC  = (__nv_bfloat16*)(base + OFF_WKC);
    __nv_bfloat16* wvC  = (__nv_bfloat16*)(base + OFF_WVC);
    __nv_bfloat16* woC  = (__nv_bfloat16*)(base + OFF_WOC);
    __nv_bfloat16* w1C  = (__nv_bfloat16*)(base + OFF_W1C);
    __nv_bfloat16* w3C  = (__nv_bfloat16*)(base + OFF_W3C);
    __nv_bfloat16* w2C  = (__nv_bfloat16*)(base + OFF_W2C);

    cudaFuncSetAttribute(mma_gemm_kernel<2>, cudaFuncAttributeMaxDynamicSharedMemorySize, GSMEM);
    cudaFuncSetAttribute(mma_gemm_kernel<3>, cudaFuncAttributeMaxDynamicSharedMemorySize, GSMEM);
    cudaFuncSetAttribute(ffn_gemm_kernel, cudaFuncAttributeMaxDynamicSharedMemorySize, FSMEM);
    cudaFuncSetAttribute(attn_mma_kernel, cudaFuncAttributeMaxDynamicSharedMemorySize, ATT_SMEM);

    // weight converts (pure streaming, same layout)
    convert2_kernel<<<dim3(DIM*DIM/2048, 2), 256>>>(wq, wk, wqC, wkC);
    convert2_kernel<<<dim3(DIM*DIM/2048, 2), 256>>>(wv, wo, wvC, woC);
    convert3_kernel<<<dim3(DIM*HID/2048, 3), 256>>>(w1, w3, w2, w1C, w3C, w2C);

    // adaLN: split-K partials + deterministic reduce
    adaln_part_kernel<<<dim3(MCOLS/256, KSPLIT), 256>>>(adaln_in, ada_w, mpart);
    adaln_reduce_kernel<<<MCOLS/256, 256>>>(mpart, ada_b, m);

    rmsmod_kernel<<<RR, 256>>>(x, attn_norm_w, m, 0, DIM, hbf);

    // fused QKV projection
    mma_gemm_kernel<3><<<dim3(3*DIM/128, RR/128), 256, GSMEM>>>(
        hbf, wqC, wkC, wvC, DIM, qf, kf, vbf, nullptr, nullptr, 0, RR, DIM, DIM);

    lnrope2_kernel<<<dim3(RR, 2), 256>>>(qf, kf, q_norm_w, q_norm_b, k_norm_w, k_norm_b,
                                         cosT, sinT, qbf, kbf);

    attn_mma_kernel<<<dim3(SEQ/128, NH, BB), 256, ATT_SMEM>>>(qbf, kbf, vbf, abf);

    // wo projection + fused gated residual: xmid = x + gate_msa * (attn@wo)
    mma_gemm_kernel<2><<<dim3(DIM/128, RR/128), 256, GSMEM>>>(
        abf, woC, nullptr, nullptr, DIM, xmid, nullptr, nullptr, x, m, 2*DIM, RR, DIM, DIM);

    rmsmod_kernel<<<RR, 256>>>(xmid, ffn_norm_w, m, 3*DIM, 4*DIM, hbf);

    // fused dual FFN gemm: g1bf = bf16(silu(h@w1) * (h@w3))
    ffn_gemm_kernel<<<dim3(HID/64, RR/128), 256, FSMEM>>>(hbf, w1C, w3C, g1bf, RR, HID, DIM);

    // w2 projection + fused gated residual: out = xmid + gate_mlp * (g@w2)
    mma_gemm_kernel<2><<<dim3(DIM/128, RR/128), 256, GSMEM>>>(
        g1bf, w2C, nullptr, nullptr, DIM, out, nullptr, nullptr, xmid, m, 5*DIM, RR, DIM, HID);
}

// round 13
// speedup vs baseline: 1.0409x; 1.0409x over previous
#include <cuda_runtime.h>
#include <cuda_bf16.h>
#include <math.h>
#include <stdint.h>

#define BB 2
#define SEQ 2048
#define RR (BB*SEQ)          // 4096 rows
#define DIM 1024
#define HID 2816
#define NH 16
#define HD 64
#define MCOLS (6*DIM)        // 6144
#define KSPLIT 32

// ---- scratch (float units) ----
#define SZ_M     16384
#define SZ_MPART (KSPLIT*2*MCOLS)
#define SZ_RD    (RR*DIM)
#define SZ_RDH   (RR*DIM/2)
#define SZ_RHH   (RR*HID/2)
#define SZ_WS    (DIM*DIM/2)
#define SZ_WB    (DIM*HID/2)

#define OFF_M    0
#define OFF_MPART (OFF_M + SZ_M)
#define OFF_HBF  (OFF_MPART + SZ_MPART)
#define OFF_QF   (OFF_HBF + SZ_RDH)
#define OFF_KF   (OFF_QF + SZ_RD)
#define OFF_QBF  (OFF_KF + SZ_RD)
#define OFF_KBF  (OFF_QBF + SZ_RDH)
#define OFF_VBF  (OFF_KBF + SZ_RDH)
#define OFF_ABF  (OFF_VBF + SZ_RDH)
#define OFF_XMID (OFF_ABF + SZ_RDH)
#define OFF_G1BF (OFF_XMID + SZ_RD)
#define OFF_WQC  (OFF_G1BF + SZ_RHH)
#define OFF_WKC  (OFF_WQC + SZ_WS)
#define OFF_WVC  (OFF_WKC + SZ_WS)
#define OFF_WOC  (OFF_WVC + SZ_WS)
#define OFF_W1C  (OFF_WOC + SZ_WS)
#define OFF_W3C  (OFF_W1C + SZ_WB)
#define OFF_W2C  (OFF_W3C + SZ_WB)
#define TOTAL_F  (OFF_W2C + SZ_WB)

__device__ float g_buf[TOTAL_F];

__device__ __forceinline__ uint32_t smem_u32(const void* p) {
    uint32_t a;
    asm("{ .reg .u64 t; cvta.to.shared.u64 t, %1; cvt.u32.u64 %0, t; }" : "=r"(a) : "l"(p));
    return a;
}

// ===========================================================================
// adaLN split-K (32 splits of 32 k each) + deterministic reduce
// ===========================================================================
__global__ __launch_bounds__(256) void adaln_part_kernel(
    const float* __restrict__ a, const float* __restrict__ W,
    float* __restrict__ mpart)
{
    __shared__ float act0[32], act1[32];
    int j = blockIdx.x * 256 + threadIdx.x;
    int k0 = blockIdx.y * 32;
    if (threadIdx.x < 32) {
        float v = a[k0 + threadIdx.x];
        act0[threadIdx.x] = v / (1.f + __expf(-v));
    } else if (threadIdx.x < 64) {
        float v = a[DIM + k0 + threadIdx.x - 32];
        act1[threadIdx.x - 32] = v / (1.f + __expf(-v));
    }
    __syncthreads();
    float acc0 = 0.f, acc1 = 0.f;
    const float* Wp = W + (size_t)k0 * MCOLS + j;
    #pragma unroll 8
    for (int k = 0; k < 32; k++) {
        float w = Wp[(size_t)k * MCOLS];
        acc0 += act0[k] * w;
        acc1 += act1[k] * w;
    }
    mpart[(blockIdx.y*2 + 0)*MCOLS + j] = acc0;
    mpart[(blockIdx.y*2 + 1)*MCOLS + j] = acc1;
}

__global__ __launch_bounds__(256) void adaln_reduce_kernel(
    const float* __restrict__ mpart, const float* __restrict__ bias,
    float* __restrict__ m)
{
    int j = blockIdx.x * 256 + threadIdx.x;
    float b = bias[j];
    float s0 = b, s1 = b;
    #pragma unroll
    for (int kz = 0; kz < KSPLIT; kz++) {
        s0 += mpart[(kz*2 + 0)*MCOLS + j];
        s1 += mpart[(kz*2 + 1)*MCOLS + j];
    }
    m[j] = s0;
    m[MCOLS + j] = s1;
}

// ===========================================================================
// single streaming fp32 -> bf16 convert for all 7 weight matrices
// blockIdx.y: 0..3 = DIM*DIM mats, 4..6 = DIM*HID mats
// ===========================================================================
__global__ __launch_bounds__(256) void convert_all_kernel(
    const float* __restrict__ wq, const float* __restrict__ wk,
    const float* __restrict__ wv, const float* __restrict__ wo,
    const float* __restrict__ w1, const float* __restrict__ w3,
    const float* __restrict__ w2,
    __nv_bfloat16* __restrict__ base_small, __nv_bfloat16* __restrict__ base_big)
{
    int sel = blockIdx.y;
    const float* s;
    __nv_bfloat16* d;
    int nelem;
    if (sel < 4) {
        s = (sel == 0) ? wq : (sel == 1) ? wk : (sel == 2) ? wv : wo;
        d = base_small + (size_t)sel * (DIM*DIM);
        nelem = DIM*DIM;
    } else {
        s = (sel == 4) ? w1 : (sel == 5) ? w3 : w2;
        d = base_big + (size_t)(sel-4) * (DIM*HID);
        nelem = DIM*HID;
    }
    int i = (blockIdx.x*256 + threadIdx.x)*8;
    if (i >= nelem) return;
    float4 a = *(const float4*)(s + i);
    float4 b = *(const float4*)(s + i + 4);
    __nv_bfloat162 p0 = __floats2bfloat162_rn(a.x, a.y);
    __nv_bfloat162 p1 = __floats2bfloat162_rn(a.z, a.w);
    __nv_bfloat162 p2 = __floats2bfloat162_rn(b.x, b.y);
    __nv_bfloat162 p3 = __floats2bfloat162_rn(b.z, b.w);
    uint4 o;
    o.x = *(uint32_t*)&p0; o.y = *(uint32_t*)&p1;
    o.z = *(uint32_t*)&p2; o.w = *(uint32_t*)&p3;
    *(uint4*)(d + i) = o;
}

// ===========================================================================
// rmsnorm + modulate -> bf16
// ===========================================================================
__global__ __launch_bounds__(256) void rmsmod_kernel(
    const float* __restrict__ src, const float* __restrict__ w,
    const float* __restrict__ m, int shift_off, int scale_off,
    __nv_bfloat16* __restrict__ dst)
{
    __shared__ float red[256];
    int row = blockIdx.x;
    int b = row >> 11;
    int tid = threadIdx.x;
    float4 v = ((const float4*)(src + (size_t)row*DIM))[tid];
    red[tid] = v.x*v.x + v.y*v.y + v.z*v.z + v.w*v.w;
    __syncthreads();
    for (int s = 128; s > 0; s >>= 1) {
        if (tid < s) red[tid] += red[tid+s];
        __syncthreads();
    }
    float rms = rsqrtf(red[0] * (1.f/DIM) + 1e-5f);
    int d = tid * 4;
    float4 wv = *(const float4*)(w + d);
    float4 sh = *(const float4*)(m + b*MCOLS + shift_off + d);
    float4 sc = *(const float4*)(m + b*MCOLS + scale_off + d);
    float o0 = v.x*rms*wv.x*(1.f+sc.x) + sh.x;
    float o1 = v.y*rms*wv.y*(1.f+sc.y) + sh.y;
    float o2 = v.z*rms*wv.z*(1.f+sc.z) + sh.z;
    float o3 = v.w*rms*wv.w*(1.f+sc.w) + sh.w;
    __nv_bfloat162* dp = (__nv_bfloat162*)(dst + (size_t)row*DIM);
    dp[tid*2]   = __floats2bfloat162_rn(o0, o1);
    dp[tid*2+1] = __floats2bfloat162_rn(o2, o3);
}

// ===========================================================================
// bf16 mma GEMM, BK=64, 3-stage cp.async, 2 CTAs/SM.
// MODE 2: C = xres + gate*acc (fp32). MODE 3: fused QKV.
// ===========================================================================
#define GSMEM (3*32768)

template<int MODE>
__global__ __launch_bounds__(256, 2) void mma_gemm_kernel(
    const __nv_bfloat16* __restrict__ A,
    const __nv_bfloat16* __restrict__ B0,
    const __nv_bfloat16* __restrict__ B1m,
    const __nv_bfloat16* __restrict__ B2m,
    int ldb,
    float* __restrict__ Cf,
    float* __restrict__ kf,
    __nv_bfloat16* __restrict__ vbf,
    const float* __restrict__ xres,
    const float* __restrict__ mvec, int gate_off,
    int M, int N, int K)
{
    extern __shared__ __align__(128) char smch[];
    uint32_t sb = smem_u32(smch);
    int tid = threadIdx.x;
    int wid = tid >> 5, lid = tid & 31;
    int warp_m = wid & 1;
    int warp_n = wid >> 1;
    int row0 = blockIdx.y * 128;
    int col0 = blockIdx.x * 128;
    int iters = K >> 6;

    const __nv_bfloat16* B = B0;
    int msel = 0, colB = col0;
    if (MODE == 3) {
        msel = col0 >> 10;
        colB = col0 & 1023;
        B = (msel == 0) ? B0 : (msel == 1) ? B1m : B2m;
    }

    uint32_t soA[4]; const char* gA[4];
    #pragma unroll
    for (int i = 0; i < 4; i++) {
        int cid = tid + 256*i;
        int row = cid >> 3, ch = cid & 7;
        soA[i] = row*128 + ((ch ^ (row & 7)) << 4);
        gA[i] = (const char*)(A + (size_t)(row0 + row)*K) + ch*16;
    }
    uint32_t soB[4]; const char* gB[4];
    #pragma unroll
    for (int i = 0; i < 4; i++) {
        int cid = tid + 256*i;
        int rb = cid >> 4, cb = cid & 15;
        soB[i] = rb*256 + ((cb ^ (rb & 7)) << 4);
        gB[i] = (const char*)(B + (size_t)rb*ldb + colB) + cb*16;
    }
    size_t bstep = (size_t)64 * ldb * 2;

    float acc[4][4][4];
    #pragma unroll
    for (int i = 0; i < 4; i++)
        #pragma unroll
        for (int j = 0; j < 4; j++)
            #pragma unroll
            for (int q = 0; q < 4; q++) acc[i][j][q] = 0.f;

    int arow[4];
    #pragma unroll
    for (int mt = 0; mt < 4; mt++)
        arow[mt] = warp_m*64 + mt*16 + (lid & 15);
    int ahalf = lid >> 4;
    int matq = lid >> 3, r8 = lid & 7;

    #pragma unroll
    for (int p = 0; p < 2; p++) {
        uint32_t tA = sb + p*32768, tB = tA + 16384;
        #pragma unroll
        for (int i = 0; i < 4; i++) {
            asm volatile("cp.async.cg.shared.global [%0], [%1], 16;" :: "r"(tA+soA[i]), "l"(gA[i] + p*128));
            asm volatile("cp.async.cg.shared.global [%0], [%1], 16;" :: "r"(tB+soB[i]), "l"(gB[i] + p*bstep));
        }
        asm volatile("cp.async.commit_group;");
    }

    int sidx = 0, pidx = 2;
    for (int kt = 0; kt < iters; kt++) {
        if (kt < iters-1) asm volatile("cp.async.wait_group 1;" ::: "memory");
        else              asm volatile("cp.async.wait_group 0;" ::: "memory");
        __syncthreads();

        if (kt + 2 < iters) {
            uint32_t tA = sb + pidx*32768, tB = tA + 16384;
            size_t ka = (size_t)(kt + 2) * 128;
            size_t kb = (size_t)(kt + 2) * bstep;
            #pragma unroll
            for (int i = 0; i < 4; i++) {
                asm volatile("cp.async.cg.shared.global [%0], [%1], 16;" :: "r"(tA+soA[i]), "l"(gA[i]+ka));
                asm volatile("cp.async.cg.shared.global [%0], [%1], 16;" :: "r"(tB+soB[i]), "l"(gB[i]+kb));
            }
            asm volatile("cp.async.commit_group;");
        }

        uint32_t sA = sb + sidx*32768, sB = sA + 16384;
        #pragma unroll
        for (int ks = 0; ks < 4; ks++) {
            uint32_t a[4][4], b[4][2];
            #pragma unroll
            for (int mt = 0; mt < 4; mt++) {
                int row = arow[mt];
                int ck = ks*2 + ahalf;
                uint32_t ad = sA + row*128 + ((ck ^ (row & 7)) << 4);
                asm volatile("ldmatrix.sync.aligned.m8n8.x4.shared.b16 {%0,%1,%2,%3}, [%4];"
                    : "=r"(a[mt][0]), "=r"(a[mt][1]), "=r"(a[mt][2]), "=r"(a[mt][3]) : "r"(ad));
            }
            #pragma unroll
            for (int nt2 = 0; nt2 < 2; nt2++) {
                int krow = ks*16 + ((matq & 1) << 3) + r8;
                int ch = warp_n*4 + nt2*2 + (matq >> 1);
                uint32_t ad = sB + krow*256 + ((ch ^ (krow & 7)) << 4);
                asm volatile("ldmatrix.sync.aligned.m8n8.x4.trans.shared.b16 {%0,%1,%2,%3}, [%4];"
                    : "=r"(b[nt2*2][0]), "=r"(b[nt2*2][1]),
                      "=r"(b[nt2*2+1][0]), "=r"(b[nt2*2+1][1]) : "r"(ad));
            }
            #pragma unroll
            for (int mt = 0; mt < 4; mt++)
                #pragma unroll
                for (int nt = 0; nt < 4; nt++) {
                    asm volatile(
                        "mma.sync.aligned.m16n8k16.row.col.f32.bf16.bf16.f32 "
                        "{%0,%1,%2,%3}, {%4,%5,%6,%7}, {%8,%9}, {%0,%1,%2,%3};"
                        : "+f"(acc[mt][nt][0]), "+f"(acc[mt][nt][1]),
                          "+f"(acc[mt][nt][2]), "+f"(acc[mt][nt][3])
                        : "r"(a[mt][0]), "r"(a[mt][1]), "r"(a[mt][2]), "r"(a[mt][3]),
                          "r"(b[nt][0]), "r"(b[nt][1]));
                }
        }
        sidx = (sidx == 2) ? 0 : sidx + 1;
        pidx = (pidx == 2) ? 0 : pidx + 1;
    }

    int lr = lid >> 2;
    int lc = (lid & 3) * 2;
    if (MODE == 2) {
        int bsel = row0 >> 11;
        const float* gv = mvec + bsel*MCOLS + gate_off;
        #pragma unroll
        for (int mt = 0; mt < 4; mt++) {
            size_t mrow = (size_t)(row0 + warp_m*64 + mt*16 + lr);
            #pragma unroll
            for (int nt = 0; nt < 4; nt++) {
                int col = col0 + warp_n*32 + nt*8 + lc;
                float2 g = *(const float2*)(gv + col);
                float2 x0 = *(const float2*)(xres + mrow*N + col);
                float2 x1 = *(const float2*)(xres + (mrow+8)*N + col);
                *(float2*)(Cf + mrow*N + col) =
                    make_float2(x0.x + g.x*acc[mt][nt][0], x0.y + g.y*acc[mt][nt][1]);
                *(float2*)(Cf + (mrow+8)*N + col) =
                    make_float2(x1.x + g.x*acc[mt][nt][2], x1.y + g.y*acc[mt][nt][3]);
            }
        }
    } else {  // MODE 3
        #pragma unroll
        for (int mt = 0; mt < 4; mt++) {
            size_t mrow = (size_t)(row0 + warp_m*64 + mt*16 + lr);
            #pragma unroll
            for (int nt = 0; nt < 4; nt++) {
                int col = colB + warp_n*32 + nt*8 + lc;
                if (msel == 2) {
                    *(__nv_bfloat162*)(vbf + mrow*DIM + col) =
                        __floats2bfloat162_rn(acc[mt][nt][0], acc[mt][nt][1]);
                    *(__nv_bfloat162*)(vbf + (mrow+8)*DIM + col) =
                        __floats2bfloat162_rn(acc[mt][nt][2], acc[mt][nt][3]);
                } else {
                    float* dst = msel ? kf : Cf;
                    *(float2*)(dst + mrow*DIM + col) =
                        make_float2(acc[mt][nt][0], acc[mt][nt][1]);
                    *(float2*)(dst + (mrow+8)*DIM + col) =
                        make_float2(acc[mt][nt][2], acc[mt][nt][3]);
                }
            }
        }
    }
}

// ===========================================================================
// Fused FFN dual GEMM, BK=64, 2 CTAs/SM: g = bf16( silu(A@W1) * (A@W3) )
// ===========================================================================
#define FSMEM (3*32768)

__global__ __launch_bounds__(256, 2) void ffn_gemm_kernel(
    const __nv_bfloat16* __restrict__ A,
    const __nv_bfloat16* __restrict__ W1c,
    const __nv_bfloat16* __restrict__ W3c,
    __nv_bfloat16* __restrict__ Og, int M, int N, int K)
{
    extern __shared__ __align__(128) char smch[];
    uint32_t sb = smem_u32(smch);
    int tid = threadIdx.x;
    int wid = tid >> 5, lid = tid & 31;
    int warp_m = wid & 1;
    int warp_n = wid >> 1;
    int row0 = blockIdx.y * 128;
    int col0 = blockIdx.x * 64;
    int iters = K >> 6;

    uint32_t soA[4]; const char* gA[4];
    #pragma unroll
    for (int i = 0; i < 4; i++) {
        int cid = tid + 256*i;
        int row = cid >> 3, ch = cid & 7;
        soA[i] = row*128 + ((ch ^ (row & 7)) << 4);
        gA[i] = (const char*)(A + (size_t)(row0 + row)*K) + ch*16;
    }
    uint32_t soB[2]; const char *g1[2], *g3[2];
    #pragma unroll
    for (int i = 0; i < 2; i++) {
        int cid = tid + 256*i;
        int rb = cid >> 3, cb = cid & 7;
        soB[i] = rb*128 + ((cb ^ (rb & 7)) << 4);
        g1[i] = (const char*)(W1c + (size_t)rb*N + col0) + cb*16;
        g3[i] = (const char*)(W3c + (size_t)rb*N + col0) + cb*16;
    }
    size_t bstep = (size_t)64 * N * 2;

    float acc1[4][2][4], acc3[4][2][4];
    #pragma unroll
    for (int i = 0; i < 4; i++)
        #pragma unroll
        for (int j = 0; j < 2; j++)
            #pragma unroll
            for (int q = 0; q < 4; q++) { acc1[i][j][q] = 0.f; acc3[i][j][q] = 0.f; }

    int arow[4];
    #pragma unroll
    for (int mt = 0; mt < 4; mt++)
        arow[mt] = warp_m*64 + mt*16 + (lid & 15);
    int ahalf = lid >> 4;
    int matq = lid >> 3, r8 = lid & 7;

    #pragma unroll
    for (int p = 0; p < 2; p++) {
        uint32_t tA = sb + p*32768, tB1 = tA + 16384, tB3 = tA + 24576;
        #pragma unroll
        for (int i = 0; i < 4; i++)
            asm volatile("cp.async.cg.shared.global [%0], [%1], 16;" :: "r"(tA+soA[i]), "l"(gA[i] + p*128));
        #pragma unroll
        for (int i = 0; i < 2; i++) {
            asm volatile("cp.async.cg.shared.global [%0], [%1], 16;" :: "r"(tB1+soB[i]), "l"(g1[i] + p*bstep));
            asm volatile("cp.async.cg.shared.global [%0], [%1], 16;" :: "r"(tB3+soB[i]), "l"(g3[i] + p*bstep));
        }
        asm volatile("cp.async.commit_group;");
    }

    int sidx = 0, pidx = 2;
    for (int kt = 0; kt < iters; kt++) {
        if (kt < iters-1) asm volatile("cp.async.wait_group 1;" ::: "memory");
        else              asm volatile("cp.async.wait_group 0;" ::: "memory");
        __syncthreads();

        if (kt + 2 < iters) {
            uint32_t tA = sb + pidx*32768, tB1 = tA + 16384, tB3 = tA + 24576;
            size_t ka = (size_t)(kt + 2) * 128;
            size_t kb = (size_t)(kt + 2) * bstep;
            #pragma unroll
            for (int i = 0; i < 4; i++)
                asm volatile("cp.async.cg.shared.global [%0], [%1], 16;" :: "r"(tA+soA[i]), "l"(gA[i]+ka));
            #pragma unroll
            for (int i = 0; i < 2; i++) {
                asm volatile("cp.async.cg.shared.global [%0], [%1], 16;" :: "r"(tB1+soB[i]), "l"(g1[i]+kb));
                asm volatile("cp.async.cg.shared.global [%0], [%1], 16;" :: "r"(tB3+soB[i]), "l"(g3[i]+kb));
            }
            asm volatile("cp.async.commit_group;");
        }

        uint32_t sA = sb + sidx*32768, sB1 = sA + 16384, sB3 = sA + 24576;
        #pragma unroll
        for (int ks = 0; ks < 4; ks++) {
            uint32_t a[4][4];
            #pragma unroll
            for (int mt = 0; mt < 4; mt++) {
                int row = arow[mt];
                int ck = ks*2 + ahalf;
                uint32_t ad = sA + row*128 + ((ck ^ (row & 7)) << 4);
                asm volatile("ldmatrix.sync.aligned.m8n8.x4.shared.b16 {%0,%1,%2,%3}, [%4];"
                    : "=r"(a[mt][0]), "=r"(a[mt][1]), "=r"(a[mt][2]), "=r"(a[mt][3]) : "r"(ad));
            }
            int krow = ks*16 + ((matq & 1) << 3) + r8;
            int ch = warp_n*2 + (matq >> 1);
            uint32_t swoff = krow*128 + ((ch ^ (krow & 7)) << 4);
            uint32_t b1[4], b3[4];
            asm volatile("ldmatrix.sync.aligned.m8n8.x4.trans.shared.b16 {%0,%1,%2,%3}, [%4];"
                : "=r"(b1[0]), "=r"(b1[1]), "=r"(b1[2]), "=r"(b1[3]) : "r"(sB1 + swoff));
            asm volatile("ldmatrix.sync.aligned.m8n8.x4.trans.shared.b16 {%0,%1,%2,%3}, [%4];"
                : "=r"(b3[0]), "=r"(b3[1]), "=r"(b3[2]), "=r"(b3[3]) : "r"(sB3 + swoff));
            #pragma unroll
            for (int mt = 0; mt < 4; mt++) {
                #pragma unroll
                for (int nt = 0; nt < 2; nt++) {
                    asm volatile(
                        "mma.sync.aligned.m16n8k16.row.col.f32.bf16.bf16.f32 "
                        "{%0,%1,%2,%3}, {%4,%5,%6,%7}, {%8,%9}, {%0,%1,%2,%3};"
                        : "+f"(acc1[mt][nt][0]), "+f"(acc1[mt][nt][1]),
                          "+f"(acc1[mt][nt][2]), "+f"(acc1[mt][nt][3])
                        : "r"(a[mt][0]), "r"(a[mt][1]), "r"(a[mt][2]), "r"(a[mt][3]),
                          "r"(b1[nt*2]), "r"(b1[nt*2+1]));
                    asm volatile(
                        "mma.sync.aligned.m16n8k16.row.col.f32.bf16.bf16.f32 "
                        "{%0,%1,%2,%3}, {%4,%5,%6,%7}, {%8,%9}, {%0,%1,%2,%3};"
                        : "+f"(acc3[mt][nt][0]), "+f"(acc3[mt][nt][1]),
                          "+f"(acc3[mt][nt][2]), "+f"(acc3[mt][nt][3])
                        : "r"(a[mt][0]), "r"(a[mt][1]), "r"(a[mt][2]), "r"(a[mt][3]),
                          "r"(b3[nt*2]), "r"(b3[nt*2+1]));
                }
            }
        }
        sidx = (sidx == 2) ? 0 : sidx + 1;
        pidx = (pidx == 2) ? 0 : pidx + 1;
    }

    int lr = lid >> 2;
    int lc = (lid & 3) * 2;
    #pragma unroll
    for (int mt = 0; mt < 4; mt++) {
        size_t mrow = (size_t)(row0 + warp_m*64 + mt*16 + lr);
        #pragma unroll
        for (int nt = 0; nt < 2; nt++) {
            int col = col0 + warp_n*16 + nt*8 + lc;
            float s0 = acc1[mt][nt][0], s1 = acc1[mt][nt][1];
            float s2 = acc1[mt][nt][2], s3 = acc1[mt][nt][3];
            float o0 = s0 / (1.f + __expf(-s0)) * acc3[mt][nt][0];
            float o1 = s1 / (1.f + __expf(-s1)) * acc3[mt][nt][1];
            float o2 = s2 / (1.f + __expf(-s2)) * acc3[mt][nt][2];
            float o3 = s3 / (1.f + __expf(-s3)) * acc3[mt][nt][3];
            *(__nv_bfloat162*)(Og + mrow*N + col)     = __floats2bfloat162_rn(o0, o1);
            *(__nv_bfloat162*)(Og + (mrow+8)*N + col) = __floats2bfloat162_rn(o2, o3);
        }
    }
}

// ===========================================================================
// layernorm + RoPE for q and k in one launch
// ===========================================================================
__global__ __launch_bounds__(256) void lnrope2_kernel(
    const float* __restrict__ qf, const float* __restrict__ kf,
    const float* __restrict__ qw, const float* __restrict__ qb,
    const float* __restrict__ kw, const float* __restrict__ kb,
    const float* __restrict__ cosT, const float* __restrict__ sinT,
    __nv_bfloat16* __restrict__ qbf, __nv_bfloat16* __restrict__ kbf)
{
    __shared__ float redm[256], redv[256];
    int sel = blockIdx.y;
    const float* t = sel ? kf : qf;
    const float* w = sel ? kw : qw;
    const float* bvec = sel ? kb : qb;
    __nv_bfloat16* dst = sel ? kbf : qbf;
    int row = blockIdx.x;
    int s = row & (SEQ-1);
    int tid = threadIdx.x;
    float4 v = ((const float4*)(t + (size_t)row*DIM))[tid];
    redm[tid] = v.x + v.y + v.z + v.w;
    redv[tid] = v.x*v.x + v.y*v.y + v.z*v.z + v.w*v.w;
    __syncthreads();
    for (int st = 128; st > 0; st >>= 1) {
        if (tid < st) { redm[tid] += redm[tid+st]; redv[tid] += redv[tid+st]; }
        __syncthreads();
    }
    float mu = redm[0] * (1.f/DIM);
    float var = redv[0] * (1.f/DIM) - mu*mu;
    float rs = rsqrtf(var + 1e-5f);
    int d = tid*4;
    float4 wv = *(const float4*)(w + d);
    float4 bv = *(const float4*)(bvec + d);
    float y0 = (v.x-mu)*rs*wv.x + bv.x;
    float y1 = (v.y-mu)*rs*wv.y + bv.y;
    float y2 = (v.z-mu)*rs*wv.z + bv.z;
    float y3 = (v.w-mu)*rs*wv.w + bv.w;
    int i0 = (d & 63) >> 1;
    float c0 = cosT[s*32 + i0],   s0 = sinT[s*32 + i0];
    float c1 = cosT[s*32 + i0+1], s1 = sinT[s*32 + i0+1];
    float o0 = y0*c0 - y1*s0;
    float o1 = y0*s0 + y1*c0;
    float o2 = y2*c1 - y3*s1;
    float o3 = y2*s1 + y3*c1;
    __nv_bfloat162* dp = (__nv_bfloat162*)(dst + (size_t)row*DIM);
    dp[tid*2]   = __floats2bfloat162_rn(o0, o1);
    dp[tid*2+1] = __floats2bfloat162_rn(o2, o3);
}

// ===========================================================================
// Tensor-core flash attention — now 2 CTAs/SM
// ===========================================================================
#define ATT_SMEM 49152

__global__ __launch_bounds__(256, 2) void attn_mma_kernel(
    const __nv_bfloat16* __restrict__ q, const __nv_bfloat16* __restrict__ k,
    const __nv_bfloat16* __restrict__ v, __nv_bfloat16* __restrict__ o)
{
    extern __shared__ __align__(128) char smch[];
    uint32_t sb = smem_u32(smch);
    const uint32_t sq  = sb;
    const uint32_t sk0 = sb + 16384;
    const uint32_t sv0 = sb + 32768;
    int tid = threadIdx.x, wid = tid >> 5, lid = tid & 31;
    int qt = blockIdx.x, h = blockIdx.y, b = blockIdx.z;
    int hoffb = h * HD * 2;
    int qbase = b*SEQ + qt*128;
    int kbb   = b*SEQ;

    #pragma unroll
    for (int i = 0; i < 4; i++) {
        int cid = tid + 256*i;
        int row = cid >> 3, ch = cid & 7;
        const char* g = (const char*)(q + (size_t)(qbase+row)*DIM) + hoffb + ch*16;
        uint32_t so = sq + row*128 + ((ch ^ (row & 7)) << 4);
        asm volatile("cp.async.cg.shared.global [%0], [%1], 16;" :: "r"(so), "l"(g));
    }
    #pragma unroll
    for (int i = 0; i < 2; i++) {
        int cid = tid + 256*i;
        int row = cid >> 3, ch = cid & 7;
        uint32_t so = row*128 + ((ch ^ (row & 7)) << 4);
        const char* gk = (const char*)(k + (size_t)(kbb+row)*DIM) + hoffb + ch*16;
        const char* gv = (const char*)(v + (size_t)(kbb+row)*DIM) + hoffb + ch*16;
        asm volatile("cp.async.cg.shared.global [%0], [%1], 16;" :: "r"(sk0+so), "l"(gk));
        asm volatile("cp.async.cg.shared.global [%0], [%1], 16;" :: "r"(sv0+so), "l"(gv));
    }
    asm volatile("cp.async.commit_group;");

    int wr = wid * 16;
    uint32_t qf[4][4];
    float oacc[8][4];
    #pragma unroll
    for (int j = 0; j < 8; j++)
        #pragma unroll
        for (int i = 0; i < 4; i++) oacc[j][i] = 0.f;
    float m0 = -INFINITY, m1 = -INFINITY, l0 = 0.f, l1 = 0.f;

    for (int kt = 0; kt < SEQ/64; kt++) {
        int s = kt & 1;
        if (kt + 1 < SEQ/64) {
            int ns = s ^ 1;
            int kb2 = kbb + (kt+1)*64;
            #pragma unroll
            for (int i = 0; i < 2; i++) {
                int cid = tid + 256*i;
                int row = cid >> 3, ch = cid & 7;
                uint32_t so = row*128 + ((ch ^ (row & 7)) << 4);
                const char* gk = (const char*)(k + (size_t)(kb2+row)*DIM) + hoffb + ch*16;
                const char* gv = (const char*)(v + (size_t)(kb2+row)*DIM) + hoffb + ch*16;
                asm volatile("cp.async.cg.shared.global [%0], [%1], 16;" :: "r"(sk0+ns*8192+so), "l"(gk));
                asm volatile("cp.async.cg.shared.global [%0], [%1], 16;" :: "r"(sv0+ns*8192+so), "l"(gv));
            }
            asm volatile("cp.async.commit_group;");
            asm volatile("cp.async.wait_group 1;" ::: "memory");
        } else {
            asm volatile("cp.async.wait_group 0;" ::: "memory");
        }
        __syncthreads();

        if (kt == 0) {
            int arow2 = wr + (lid & 15);
            #pragma unroll
            for (int s2 = 0; s2 < 4; s2++) {
                int ch = 2*s2 + (lid >> 4);
                uint32_t ad = sq + arow2*128 + ((ch ^ (arow2 & 7)) << 4);
                asm volatile("ldmatrix.sync.aligned.m8n8.x4.shared.b16 {%0,%1,%2,%3}, [%4];"
                    : "=r"(qf[s2][0]), "=r"(qf[s2][1]), "=r"(qf[s2][2]), "=r"(qf[s2][3]) : "r"(ad));
            }
        }
        uint32_t skst = sk0 + s*8192, svst = sv0 + s*8192;

        float sa[8][4];
        #pragma unroll
        for (int j = 0; j < 8; j++)
            #pragma unroll
            for (int i = 0; i < 4; i++) sa[j][i] = 0.f;

        #pragma unroll
        for (int s2 = 0; s2 < 4; s2++) {
            #pragma unroll
            for (int p = 0; p < 4; p++) {
                int mat = lid >> 3;
                int krow = p*16 + ((mat >> 1) << 3) + (lid & 7);
                int ch = 2*s2 + (mat & 1);
                uint32_t ad = skst + krow*128 + ((ch ^ (krow & 7)) << 4);
                uint32_t b0, b1, b2, b3;
                asm volatile("ldmatrix.sync.aligned.m8n8.x4.shared.b16 {%0,%1,%2,%3}, [%4];"
                    : "=r"(b0), "=r"(b1), "=r"(b2), "=r"(b3) : "r"(ad));
                asm volatile(
                    "mma.sync.aligned.m16n8k16.row.col.f32.bf16.bf16.f32 "
                    "{%0,%1,%2,%3}, {%4,%5,%6,%7}, {%8,%9}, {%0,%1,%2,%3};"
                    : "+f"(sa[2*p][0]), "+f"(sa[2*p][1]), "+f"(sa[2*p][2]), "+f"(sa[2*p][3])
                    : "r"(qf[s2][0]), "r"(qf[s2][1]), "r"(qf[s2][2]), "r"(qf[s2][3]),
                      "r"(b0), "r"(b1));
                asm volatile(
                    "mma.sync.aligned.m16n8k16.row.col.f32.bf16.bf16.f32 "
                    "{%0,%1,%2,%3}, {%4,%5,%6,%7}, {%8,%9}, {%0,%1,%2,%3};"
                    : "+f"(sa[2*p+1][0]), "+f"(sa[2*p+1][1]), "+f"(sa[2*p+1][2]), "+f"(sa[2*p+1][3])
                    : "r"(qf[s2][0]), "r"(qf[s2][1]), "r"(qf[s2][2]), "r"(qf[s2][3]),
                      "r"(b2), "r"(b3));
            }
        }

        float mx0 = -INFINITY, mx1 = -INFINITY;
        #pragma unroll
        for (int j = 0; j < 8; j++) {
            sa[j][0] *= 0.125f; sa[j][1] *= 0.125f;
            sa[j][2] *= 0.125f; sa[j][3] *= 0.125f;
            mx0 = fmaxf(mx0, fmaxf(sa[j][0], sa[j][1]));
            mx1 = fmaxf(mx1, fmaxf(sa[j][2], sa[j][3]));
        }
        mx0 = fmaxf(mx0, __shfl_xor_sync(0xffffffffu, mx0, 1));
        mx0 = fmaxf(mx0, __shfl_xor_sync(0xffffffffu, mx0, 2));
        mx1 = fmaxf(mx1, __shfl_xor_sync(0xffffffffu, mx1, 1));
        mx1 = fmaxf(mx1, __shfl_xor_sync(0xffffffffu, mx1, 2));
        float nm0 = fmaxf(m0, mx0), nm1 = fmaxf(m1, mx1);

        float ps0 = 0.f, ps1 = 0.f;
        uint32_t pf[4][4];
        #pragma unroll
        for (int j = 0; j < 8; j++) {
            float e0 = __expf(sa[j][0] - nm0);
            float e1 = __expf(sa[j][1] - nm0);
            float e2 = __expf(sa[j][2] - nm1);
            float e3 = __expf(sa[j][3] - nm1);
            ps0 += e0 + e1; ps1 += e2 + e3;
            int s2 = j >> 1;
            __nv_bfloat162 lo = __floats2bfloat162_rn(e0, e1);
            __nv_bfloat162 hi = __floats2bfloat162_rn(e2, e3);
            if ((j & 1) == 0) {
                pf[s2][0] = *(uint32_t*)&lo;
                pf[s2][1] = *(uint32_t*)&hi;
            } else {
                pf[s2][2] = *(uint32_t*)&lo;
                pf[s2][3] = *(uint32_t*)&hi;
            }
        }
        ps0 += __shfl_xor_sync(0xffffffffu, ps0, 1);
        ps0 += __shfl_xor_sync(0xffffffffu, ps0, 2);
        ps1 += __shfl_xor_sync(0xffffffffu, ps1, 1);
        ps1 += __shfl_xor_sync(0xffffffffu, ps1, 2);

        float c0 = __expf(m0 - nm0), c1 = __expf(m1 - nm1);
        l0 = l0*c0 + ps0;  l1 = l1*c1 + ps1;
        m0 = nm0;  m1 = nm1;
        #pragma unroll
        for (int j = 0; j < 8; j++) {
            oacc[j][0] *= c0; oacc[j][1] *= c0;
            oacc[j][2] *= c1; oacc[j][3] *= c1;
        }

        #pragma unroll
        for (int s2 = 0; s2 < 4; s2++) {
            #pragma unroll
            for (int p = 0; p < 4; p++) {
                int mat = lid >> 3;
                int vrow = s2*16 + ((mat & 1) << 3) + (lid & 7);
                int ch = 2*p + (mat >> 1);
                uint32_t ad = svst + vrow*128 + ((ch ^ (vrow & 7)) << 4);
                uint32_t v0, v1, v2, v3;
                asm volatile("ldmatrix.sync.aligned.m8n8.x4.trans.shared.b16 {%0,%1,%2,%3}, [%4];"
                    : "=r"(v0), "=r"(v1), "=r"(v2), "=r"(v3) : "r"(ad));
                asm volatile(
                    "mma.sync.aligned.m16n8k16.row.col.f32.bf16.bf16.f32 "
                    "{%0,%1,%2,%3}, {%4,%5,%6,%7}, {%8,%9}, {%0,%1,%2,%3};"
                    : "+f"(oacc[2*p][0]), "+f"(oacc[2*p][1]), "+f"(oacc[2*p][2]), "+f"(oacc[2*p][3])
                    : "r"(pf[s2][0]), "r"(pf[s2][1]), "r"(pf[s2][2]), "r"(pf[s2][3]),
                      "r"(v0), "r"(v1));
                asm volatile(
                    "mma.sync.aligned.m16n8k16.row.col.f32.bf16.bf16.f32 "
                    "{%0,%1,%2,%3}, {%4,%5,%6,%7}, {%8,%9}, {%0,%1,%2,%3};"
                    : "+f"(oacc[2*p+1][0]), "+f"(oacc[2*p+1][1]), "+f"(oacc[2*p+1][2]), "+f"(oacc[2*p+1][3])
                    : "r"(pf[s2][0]), "r"(pf[s2][1]), "r"(pf[s2][2]), "r"(pf[s2][3]),
                      "r"(v2), "r"(v3));
            }
        }
        __syncthreads();
    }

    float inv0 = 1.f / l0, inv1 = 1.f / l1;
    int r = lid >> 2, c2 = (lid & 3) * 2;
    size_t row0 = (size_t)(qbase + wr + r)*DIM + h*HD + c2;
    size_t row1 = row0 + 8*DIM;
    #pragma unroll
    for (int j = 0; j < 8; j++) {
        *(__nv_bfloat162*)(o + row0 + 8*j) =
            __floats2bfloat162_rn(oacc[j][0]*inv0, oacc[j][1]*inv0);
        *(__nv_bfloat162*)(o + row1 + 8*j) =
            __floats2bfloat162_rn(oacc[j][2]*inv1, oacc[j][3]*inv1);
    }
}

// ===========================================================================
extern "C" void kernel_launch(void* const* d_in, const int* in_sizes, int n_in,
                              void* d_out, int out_size)
{
    const float* x        = (const float*)d_in[0];
    const float* adaln_in = (const float*)d_in[1];
    const float* cosT     = (const float*)d_in[2];
    const float* sinT     = (const float*)d_in[3];
    const float* wq       = (const float*)d_in[4];
    const float* wk       = (const float*)d_in[5];
    const float* wv       = (const float*)d_in[6];
    const float* wo       = (const float*)d_in[7];
    const float* q_norm_w = (const float*)d_in[8];
    const float* q_norm_b = (const float*)d_in[9];
    const float* k_norm_w = (const float*)d_in[10];
    const float* k_norm_b = (const float*)d_in[11];
    const float* attn_norm_w = (const float*)d_in[12];
    const float* ffn_norm_w  = (const float*)d_in[13];
    const float* ada_w    = (const float*)d_in[14];
    const float* ada_b    = (const float*)d_in[15];
    const float* w1       = (const float*)d_in[16];
    const float* w2       = (const float*)d_in[17];
    const float* w3       = (const float*)d_in[18];
    float* out = (float*)d_out;

    float* base = nullptr;
    cudaGetSymbolAddress((void**)&base, g_buf);
    float* m     = base + OFF_M;
    float* mpart = base + OFF_MPART;
    __nv_bfloat16* hbf  = (__nv_bfloat16*)(base + OFF_HBF);
    float* qf   = base + OFF_QF;
    float* kf   = base + OFF_KF;
    __nv_bfloat16* qbf  = (__nv_bfloat16*)(base + OFF_QBF);
    __nv_bfloat16* kbf  = (__nv_bfloat16*)(base + OFF_KBF);
    __nv_bfloat16* vbf  = (__nv_bfloat16*)(base + OFF_VBF);
    __nv_bfloat16* abf  = (__nv_bfloat16*)(base + OFF_ABF);
    float* xmid = base + OFF_XMID;
    __nv_bfloat16* g1bf = (__nv_bfloat16*)(base + OFF_G1BF);
    __nv_bfloat16* wqC  = (__nv_bfloat16*)(base + OFF_WQC);
    __nv_bfloat16* wkC  = (__nv_bfloat16*)(base + OFF_WKC);
    __nv_bfloat16* wvC  = (__nv_bfloat16*)(base + OFF_WVC);
    __nv_bfloat16* woC  = (__nv_bfloat16*)(base + OFF_WOC);
    __nv_bfloat16* w1C  = (__nv_bfloat16*)(base + OFF_W1C);
    __nv_bfloat16* w3C  = (__nv_bfloat16*)(base + OFF_W3C);
    __nv_bfloat16* w2C  = (__nv_bfloat16*)(base + OFF_W2C);

    cudaFuncSetAttribute(mma_gemm_kernel<2>, cudaFuncAttributeMaxDynamicSharedMemorySize, GSMEM);
    cudaFuncSetAttribute(mma_gemm_kernel<3>, cudaFuncAttributeMaxDynamicSharedMemorySize, GSMEM);
    cudaFuncSetAttribute(ffn_gemm_kernel, cudaFuncAttributeMaxDynamicSharedMemorySize, FSMEM);
    cudaFuncSetAttribute(attn_mma_kernel, cudaFuncAttributeMaxDynamicSharedMemorySize, ATT_SMEM);

    // all 7 weight converts in one launch (wqC..woC contiguous; w1C/w3C/w2C contiguous)
    convert_all_kernel<<<dim3(DIM*HID/2048, 7), 256>>>(
        wq, wk, wv, wo, w1, w3, w2, wqC, w1C);

    // adaLN: split-K partials + deterministic reduce
    adaln_part_kernel<<<dim3(MCOLS/256, KSPLIT), 256>>>(adaln_in, ada_w, mpart);
    adaln_reduce_kernel<<<MCOLS/256, 256>>>(mpart, ada_b, m);

    rmsmod_kernel<<<RR, 256>>>(x, attn_norm_w, m, 0, DIM, hbf);

    // fused QKV projection
    mma_gemm_kernel<3><<<dim3(3*DIM/128, RR/128), 256, GSMEM>>>(
        hbf, wqC, wkC, wvC, DIM, qf, kf, vbf, nullptr, nullptr, 0, RR, DIM, DIM);

    lnrope2_kernel<<<dim3(RR, 2), 256>>>(qf, kf, q_norm_w, q_norm_b, k_norm_w, k_norm_b,
                                         cosT, sinT, qbf, kbf);

    attn_mma_kernel<<<dim3(SEQ/128, NH, BB), 256, ATT_SMEM>>>(qbf, kbf, vbf, abf);

    // wo projection + fused gated residual: xmid = x + gate_msa * (attn@wo)
    mma_gemm_kernel<2><<<dim3(DIM/128, RR/128), 256, GSMEM>>>(
        abf, woC, nullptr, nullptr, DIM, xmid, nullptr, nullptr, x, m, 2*DIM, RR, DIM, DIM);

    rmsmod_kernel<<<RR, 256>>>(xmid, ffn_norm_w, m, 3*DIM, 4*DIM, hbf);

    // fused dual FFN gemm: g1bf = bf16(silu(h@w1) * (h@w3))
    ffn_gemm_kernel<<<dim3(HID/64, RR/128), 256, FSMEM>>>(hbf, w1C, w3C, g1bf, RR, HID, DIM);

    // w2 projection + fused gated residual: out = xmid + gate_mlp * (g@w2)
    mma_gemm_kernel<2><<<dim3(DIM/128, RR/128), 256, GSMEM>>>(
        g1bf, w2C, nullptr, nullptr, DIM, out, nullptr, nullptr, xmid, m, 5*DIM, RR, DIM, HID);
}